// round 14
// baseline (speedup 1.0000x reference)
#include <cuda_runtime.h>

#define HID 128
#define HEADS 4
#define DIM 32
#define NT 8
#define ETY 8

#define N_SRC_MAX 200000
#define N_CTR_MAX 100000
#define N_EDGE_MAX 800000
#define OSRC_LEN (N_SRC_MAX + 1024)

typedef unsigned long long u64;

__device__ __forceinline__ u64 pk2(float x, float y) {
    u64 r; asm("mov.b64 %0,{%1,%2};" : "=l"(r) : "f"(x), "f"(y)); return r;
}
__device__ __forceinline__ void up2(float& x, float& y, u64 v) {
    asm("mov.b64 {%0,%1},%2;" : "=f"(x), "=f"(y) : "l"(v));
}
__device__ __forceinline__ u64 f2fma(u64 a, u64 b, u64 c) {
    u64 d; asm("fma.rn.f32x2 %0,%1,%2,%3;" : "=l"(d) : "l"(a), "l"(b), "l"(c)); return d;
}
__device__ __forceinline__ float tf32r(float x) {
    unsigned u; asm("cvt.rna.tf32.f32 %0, %1;" : "=r"(u) : "f"(x));
    return __uint_as_float(u);
}
__device__ __forceinline__ void mma_tf32(float* c, const unsigned* a, unsigned b0, unsigned b1) {
    asm("mma.sync.aligned.m16n8k8.row.col.f32.tf32.tf32.f32 "
        "{%0,%1,%2,%3}, {%4,%5,%6,%7}, {%8,%9}, {%0,%1,%2,%3};"
        : "+f"(c[0]), "+f"(c[1]), "+f"(c[2]), "+f"(c[3])
        : "r"(a[0]), "r"(a[1]), "r"(a[2]), "r"(a[3]), "r"(b0), "r"(b1));
}

// ---------------- scratch (device globals; no runtime allocation) ----------------
__device__ float g_k[(size_t)N_SRC_MAX * HID];
__device__ float g_v[(size_t)N_SRC_MAX * HID];
__device__ float g_q[(size_t)N_CTR_MAX * HID];
__device__ float g_qa[(size_t)N_CTR_MAX * ETY * HID];   // 410MB: (A[et] q[c]) * rp/sqrt(d)
__device__ float g_vm[(size_t)N_SRC_MAX * ETY * HID];   // 820MB: v[s] @ M[et]
__device__ float g_a[(size_t)N_EDGE_MAX * HEADS];       // edge scores
__device__ int   g_dstid[N_EDGE_MAX];
__device__ int   g_osrc[OSRC_LEN];
__device__ int   g_odst[OSRC_LEN];                      // padded same as osrc (merged gemm launch)
__device__ unsigned char g_useq[(size_t)N_CTR_MAX * ETY];
__device__ unsigned char g_usev[(size_t)N_SRC_MAX * ETY];
__device__ int   g_cnt[16];
__device__ int   g_pos[16];

// ---------------- prep ----------------
__global__ void zero_kernel() {
    int i = blockIdx.x * blockDim.x + threadIdx.x;
    int stride = gridDim.x * blockDim.x;
    if (i < 16) { g_cnt[i] = 0; g_pos[i] = 0; }
    for (int j = i; j < OSRC_LEN; j += stride) { g_osrc[j] = -1; g_odst[j] = -1; }
    for (int j = i; j < N_CTR_MAX * ETY / 4; j += stride) ((unsigned*)g_useq)[j] = 0u;
    for (int j = i; j < N_SRC_MAX * ETY / 4; j += stride) ((unsigned*)g_usev)[j] = 0u;
}

// fill dst ids + mark used (center,et) and (src,et) pairs
__global__ void fill_mark_kernel(const int* __restrict__ ptr, const int* __restrict__ idx,
                                 const int* __restrict__ etype, int C) {
    int i = blockIdx.x * blockDim.x + threadIdx.x;
    int stride = gridDim.x * blockDim.x;
    for (int c = i; c < C; c += stride) {
        int e0 = ptr[c], e1 = ptr[c + 1];
        for (int e = e0; e < e1; ++e) {
            g_dstid[e] = c;
            int et = etype[e];
            int s = idx[e];
            g_useq[(size_t)c * 8 + et] = 1;
            g_usev[(size_t)s * 8 + et] = 1;
        }
    }
}

__global__ void hist_kernel(const int* __restrict__ ntype, int num_src, int num_center) {
    __shared__ int sc[16];
    if (threadIdx.x < 16) sc[threadIdx.x] = 0;
    __syncthreads();
    int n = blockIdx.x * blockDim.x + threadIdx.x;
    if (n < num_src) {
        int t = ntype[n];
        atomicAdd(&sc[t], 1);
        if (n < num_center) atomicAdd(&sc[8 + t], 1);
    }
    __syncthreads();
    if (threadIdx.x < 16 && sc[threadIdx.x]) atomicAdd(&g_cnt[threadIdx.x], sc[threadIdx.x]);
}

__global__ void offsets_kernel() {
    if (threadIdx.x == 0 && blockIdx.x == 0) {
        int off = 0;
        for (int t = 0; t < 8; t++) { g_pos[t] = off; off += ((g_cnt[t] + 63) >> 6) << 6; }
        off = 0;
        for (int t = 0; t < 8; t++) { g_pos[8 + t] = off; off += ((g_cnt[8 + t] + 63) >> 6) << 6; }
    }
}

__global__ void scatter_kernel(const int* __restrict__ ntype, int num_src, int num_center) {
    __shared__ int sc[16];
    __shared__ int sb[16];
    if (threadIdx.x < 16) sc[threadIdx.x] = 0;
    __syncthreads();
    int n = blockIdx.x * blockDim.x + threadIdx.x;
    int t = 0, r1 = -1, r2 = -1;
    if (n < num_src) {
        t = ntype[n];
        r1 = atomicAdd(&sc[t], 1);
        if (n < num_center) r2 = atomicAdd(&sc[8 + t], 1);
    }
    __syncthreads();
    if (threadIdx.x < 16)
        sb[threadIdx.x] = sc[threadIdx.x] ? atomicAdd(&g_pos[threadIdx.x], sc[threadIdx.x]) : 0;
    __syncthreads();
    if (r1 >= 0) g_osrc[sb[t] + r1] = n;
    if (r2 >= 0) g_odst[sb[8 + t] + r2] = n;
}

// ---------------- typed node projection: tf32 tensor-core GEMM (merged k/v/q via grid.y) ----------------
#define XS_STRIDE 132
#define WS_STRIDE 136
#define GEMM_SMEM ((64 * XS_STRIDE + 128 * WS_STRIDE) * 4)

__global__ void __launch_bounds__(256, 2) node_gemm_kernel(
    const float* __restrict__ x, const float* __restrict__ Wk,
    const float* __restrict__ Wv, const float* __restrict__ Wq,
    const int* __restrict__ ntype)
{
    extern __shared__ float sm[];
    float* xs = sm;                     // [64][132] tf32
    float* ws = sm + 64 * XS_STRIDE;    // [128][136] tf32
    const int which = blockIdx.y;
    const int* order = (which == 2) ? g_odst : g_osrc;
    float* outp = (which == 0) ? g_k : (which == 1) ? g_v : g_q;
    const float* W8 = (which == 0) ? Wk : (which == 1) ? Wv : Wq;

    const int base = blockIdx.x * 64;
    int n0 = order[base];
    if (n0 < 0) return;
    int t = ntype[n0];
    const int tid = threadIdx.x;

    const float4* Wg = (const float4*)(W8 + (size_t)t * 16384);
#pragma unroll
    for (int i = 0; i < 16; ++i) {
        int e4 = tid + i * 256;
        float4 w = Wg[e4];
        int k = e4 >> 5, n = (e4 & 31) << 2;
        float4 o = make_float4(tf32r(w.x), tf32r(w.y), tf32r(w.z), tf32r(w.w));
        *(float4*)(ws + k * WS_STRIDE + n) = o;
    }
    {
        int m = tid >> 2, q4 = tid & 3;
        int row = order[base + m];
#pragma unroll
        for (int it = 0; it < 8; ++it) {
            int k = q4 * 4 + it * 16;
            float4 xv = make_float4(0.f, 0.f, 0.f, 0.f);
            if (row >= 0) xv = *(const float4*)(x + (size_t)row * 128 + k);
            float4 o = make_float4(tf32r(xv.x), tf32r(xv.y), tf32r(xv.z), tf32r(xv.w));
            *(float4*)(xs + m * XS_STRIDE + k) = o;
        }
    }
    __syncthreads();

    const int lane = tid & 31, wid = tid >> 5;
    const int wm = (wid >> 2) * 32;
    const int wn = (wid & 3) * 32;
    const int g = lane >> 2, tig = lane & 3;

    float acc[2][4][4];
#pragma unroll
    for (int mt = 0; mt < 2; ++mt)
#pragma unroll
        for (int nt = 0; nt < 4; ++nt)
#pragma unroll
            for (int j = 0; j < 4; ++j) acc[mt][nt][j] = 0.f;

#pragma unroll 4
    for (int ks = 0; ks < 16; ++ks) {
        int kb = ks * 8;
        unsigned a[2][4];
#pragma unroll
        for (int mt = 0; mt < 2; ++mt) {
            const float* xr = xs + (wm + mt * 16 + g) * XS_STRIDE + kb;
            const float* xr8 = xr + 8 * XS_STRIDE;
            a[mt][0] = __float_as_uint(xr[tig]);
            a[mt][1] = __float_as_uint(xr8[tig]);
            a[mt][2] = __float_as_uint(xr[tig + 4]);
            a[mt][3] = __float_as_uint(xr8[tig + 4]);
        }
#pragma unroll
        for (int nt = 0; nt < 4; ++nt) {
            const float* wr = ws + (kb + tig) * WS_STRIDE + wn + nt * 8 + g;
            unsigned b0 = __float_as_uint(wr[0]);
            unsigned b1 = __float_as_uint(wr[4 * WS_STRIDE]);
            mma_tf32(acc[0][nt], a[0], b0, b1);
            mma_tf32(acc[1][nt], a[1], b0, b1);
        }
    }

#pragma unroll
    for (int mt = 0; mt < 2; ++mt) {
        int r0 = order[base + wm + mt * 16 + g];
        int r1 = order[base + wm + mt * 16 + g + 8];
#pragma unroll
        for (int nt = 0; nt < 4; ++nt) {
            int cn = wn + nt * 8 + 2 * tig;
            if (r0 >= 0) {
                float2 o = make_float2(acc[mt][nt][0], acc[mt][nt][1]);
                *(float2*)(outp + (size_t)r0 * 128 + cn) = o;
            }
            if (r1 >= 0) {
                float2 o = make_float2(acc[mt][nt][2], acc[mt][nt][3]);
                *(float2*)(outp + (size_t)r1 * 128 + cn) = o;
            }
        }
    }
}

// ---------------- relation transform (merged qa/vm via grid.y), used-pair masked stores ----------------
// y=0 (qa): dst[c,et,h,d] = sum_f A[et,h,d,f]*q[c,h,f] * rp[h,et]/sqrt(d)
// y=1 (vm): dst[s,et,h,f] = sum_d v[s,h,d]*M[et,h,d,f]
#define QS_STRIDE 132
#define AS_STRIDE 36
#define REL_SMEM ((128 * QS_STRIDE + ETY * HEADS * DIM * AS_STRIDE) * 4)

__global__ void __launch_bounds__(256, 1) rel_kernel(
    const float* __restrict__ a_rel, const float* __restrict__ m_rel,
    const float* __restrict__ relp, int num_center, int num_src)
{
    const int mode = blockIdx.y;                 // 0 = qa, 1 = vm
    const int N = mode ? num_src : num_center;
    const int base = blockIdx.x * 128;
    if (base >= N) return;

    extern __shared__ float sm[];
    float* qs = sm;                      // [128][132] tf32 src rows
    float* as = sm + 128 * QS_STRIDE;    // [et][h][k][n] B operand
    const float inv = 0.17677669529663689f; // 1/sqrt(32)
    const int tid = threadIdx.x;

    const float* R = mode ? m_rel : a_rel;
    const float* src = mode ? g_v : g_q;
    float* dst = mode ? g_vm : g_qa;
    const unsigned char* used = mode ? g_usev : g_useq;

    for (int i = tid; i < ETY * HEADS * DIM * DIM; i += 256) {
        int et = i >> 12, h = (i >> 10) & 3, d = (i >> 5) & 31, f = i & 31;
        float sc = mode ? 1.0f : relp[h * ETY + et] * inv;
        int row = mode ? d : f;     // k-dimension
        int col = mode ? f : d;     // n-dimension
        as[((et * 4 + h) * 32 + row) * AS_STRIDE + col] = tf32r(R[i] * sc);
    }
    {
        int m = tid >> 1, half = tid & 1;
        int c = base + m;
#pragma unroll
        for (int j = 0; j < 16; ++j) {
            int k = half * 64 + j * 4;
            float4 v = make_float4(0.f, 0.f, 0.f, 0.f);
            if (c < N) v = *(const float4*)(src + (size_t)c * 128 + k);
            *(float4*)(qs + m * QS_STRIDE + k) =
                make_float4(tf32r(v.x), tf32r(v.y), tf32r(v.z), tf32r(v.w));
        }
    }
    __syncthreads();

    const int lane = tid & 31, et = tid >> 5;     // warp per edge type
    const int g = lane >> 2, tig = lane & 3;
#pragma unroll 1
    for (int h = 0; h < 4; ++h) {
        const float* ab = as + (size_t)(et * 4 + h) * 32 * AS_STRIDE;
#pragma unroll 1
        for (int mt = 0; mt < 8; ++mt) {
            int c0 = base + mt * 16 + g, c1 = c0 + 8;
            bool u0 = (c0 < N) && used[(size_t)c0 * 8 + et];
            bool u1 = (c1 < N) && used[(size_t)c1 * 8 + et];
            if (__all_sync(0xffffffffu, !u0 && !u1)) continue;   // whole 16-row tile unused
            float acc[4][4];
#pragma unroll
            for (int nt = 0; nt < 4; ++nt)
#pragma unroll
                for (int j = 0; j < 4; ++j) acc[nt][j] = 0.f;
#pragma unroll
            for (int ks = 0; ks < 4; ++ks) {
                int kb = h * 32 + ks * 8;
                const float* xr = qs + (mt * 16 + g) * QS_STRIDE + kb;
                unsigned a[4];
                a[0] = __float_as_uint(xr[tig]);
                a[1] = __float_as_uint(xr[8 * QS_STRIDE + tig]);
                a[2] = __float_as_uint(xr[tig + 4]);
                a[3] = __float_as_uint(xr[8 * QS_STRIDE + tig + 4]);
#pragma unroll
                for (int nt = 0; nt < 4; ++nt) {
                    const float* wr = ab + (ks * 8 + tig) * AS_STRIDE + nt * 8 + g;
                    mma_tf32(acc[nt], a, __float_as_uint(wr[0]),
                             __float_as_uint(wr[4 * AS_STRIDE]));
                }
            }
#pragma unroll
            for (int nt = 0; nt < 4; ++nt) {
                int col = nt * 8 + 2 * tig;
                if (u0)
                    *(float2*)(dst + (size_t)c0 * 1024 + et * 128 + h * 32 + col) =
                        make_float2(acc[nt][0], acc[nt][1]);
                if (u1)
                    *(float2*)(dst + (size_t)c1 * 1024 + et * 128 + h * 32 + col) =
                        make_float2(acc[nt][2], acc[nt][3]);
            }
        }
    }
}

// ---------------- edge scores: warp per edge, fully coalesced gathers ----------------
__global__ void __launch_bounds__(256) scores_kernel(
    const int* __restrict__ idx, const int* __restrict__ etype, int E)
{
    const unsigned FULL = 0xffffffffu;
    int w = (blockIdx.x * 256 + threadIdx.x) >> 5;   // global warp = edge
    if (w >= E) return;
    int lane = threadIdx.x & 31;
    int s = idx[w];
    int c = g_dstid[w];
    int et = etype[w];
    float4 kv = ((const float4*)(g_k + (size_t)s * HID))[lane];
    float4 qv = ((const float4*)(g_qa + ((size_t)c * 8 + et) * HID))[lane];
    u64 acc = f2fma(pk2(kv.x, kv.y), pk2(qv.x, qv.y), 0ull);
    acc = f2fma(pk2(kv.z, kv.w), pk2(qv.z, qv.w), acc);
    float lo, hi; up2(lo, hi, acc);
    float p = lo + hi;
    p += __shfl_xor_sync(FULL, p, 1);
    p += __shfl_xor_sync(FULL, p, 2);
    p += __shfl_xor_sync(FULL, p, 4);
    float val = __shfl_sync(FULL, p, (lane & 3) * 8);
    if (lane < 4) g_a[(size_t)w * 4 + lane] = val;
}

// ---------------- fused softmax + aggregation: warp per center, vm gather ----------------
__global__ void __launch_bounds__(256) fused_agg_kernel(
    const int* __restrict__ ptr, const int* __restrict__ idx,
    const int* __restrict__ etype, float* __restrict__ out, int C)
{
    const unsigned FULL = 0xffffffffu;
    const int lane = threadIdx.x & 31;
    int c = (blockIdx.x * 256 + threadIdx.x) >> 5;
    if (c >= C) return;

    int e0 = ptr[c], e1 = ptr[c + 1];
    float* ob = out + (size_t)c * HID;
    if (e1 <= e0) {
        ob[lane] = 0.f; ob[32 + lane] = 0.f; ob[64 + lane] = 0.f; ob[96 + lane] = 0.f;
        return;
    }
    int deg = e1 - e0;

    int h4 = lane & 3, el = lane >> 2;
    float mx = __int_as_float(0xff800000);
    for (int i = el; i < deg; i += 8) mx = fmaxf(mx, g_a[(size_t)(e0 + i) * 4 + h4]);
    mx = fmaxf(mx, __shfl_xor_sync(FULL, mx, 4));
    mx = fmaxf(mx, __shfl_xor_sync(FULL, mx, 8));
    mx = fmaxf(mx, __shfl_xor_sync(FULL, mx, 16));
    float den = 0.f;
    for (int i = el; i < deg; i += 8) den += __expf(g_a[(size_t)(e0 + i) * 4 + h4] - mx);
    den += __shfl_xor_sync(FULL, den, 4);
    den += __shfl_xor_sync(FULL, den, 8);
    den += __shfl_xor_sync(FULL, den, 16);
    float dinv = 1.f / den;
    float mxh[4], dih[4];
#pragma unroll
    for (int hh = 0; hh < 4; ++hh) {
        mxh[hh] = __shfl_sync(FULL, mx, hh);
        dih[hh] = __shfl_sync(FULL, dinv, hh);
    }

    float o0 = 0.f, o1 = 0.f, o2 = 0.f, o3 = 0.f;
    for (int e = e0; e < e1; ++e) {
        int s = idx[e];
        int et = etype[e];
        float4 av = *(const float4*)(g_a + (size_t)e * 4);   // broadcast
        float al0 = __expf(av.x - mxh[0]) * dih[0];
        float al1 = __expf(av.y - mxh[1]) * dih[1];
        float al2 = __expf(av.z - mxh[2]) * dih[2];
        float al3 = __expf(av.w - mxh[3]) * dih[3];
        const float* vmb = g_vm + ((size_t)s * 8 + et) * HID;  // coalesced row
        o0 = fmaf(al0, vmb[lane],      o0);
        o1 = fmaf(al1, vmb[32 + lane], o1);
        o2 = fmaf(al2, vmb[64 + lane], o2);
        o3 = fmaf(al3, vmb[96 + lane], o3);
    }
    ob[lane]      = o0;
    ob[32 + lane] = o1;
    ob[64 + lane] = o2;
    ob[96 + lane] = o3;
}

// ---------------- host launcher ----------------
extern "C" void kernel_launch(void* const* d_in, const int* in_sizes, int n_in,
                              void* d_out, int out_size)
{
    (void)out_size;
    const float* x     = (const float*)d_in[0];
    const int*   ptr   = (const int*)d_in[1];
    const int*   idx   = (const int*)d_in[2];
    const int*   ntype = (const int*)d_in[3];
    const int*   etype = (const int*)d_in[4];
    int wb = n_in - 6;
    const float* k_lin = (const float*)d_in[wb + 0];
    const float* q_lin = (const float*)d_in[wb + 1];
    const float* v_lin = (const float*)d_in[wb + 2];
    const float* a_rel = (const float*)d_in[wb + 3];
    const float* m_rel = (const float*)d_in[wb + 4];
    const float* relp  = (const float*)d_in[wb + 5];

    int num_src    = in_sizes[3];
    int num_edge   = in_sizes[2];
    int num_center = in_sizes[1] - 1;
    float* out = (float*)d_out;

    cudaFuncSetAttribute(node_gemm_kernel, cudaFuncAttributeMaxDynamicSharedMemorySize, GEMM_SMEM);
    cudaFuncSetAttribute(rel_kernel,       cudaFuncAttributeMaxDynamicSharedMemorySize, REL_SMEM);

    zero_kernel<<<600, 512>>>();
    fill_mark_kernel<<<(num_center + 255) / 256, 256>>>(ptr, idx, etype, num_center);
    hist_kernel<<<(num_src + 255) / 256, 256>>>(ntype, num_src, num_center);
    offsets_kernel<<<1, 32>>>();
    scatter_kernel<<<(num_src + 255) / 256, 256>>>(ntype, num_src, num_center);

    int tiles_src = (num_src + 63) / 64 + 8;
    dim3 ggrid(tiles_src, 3);
    node_gemm_kernel<<<ggrid, 256, GEMM_SMEM>>>(x, k_lin, v_lin, q_lin, ntype);

    dim3 rgrid((num_src + 127) / 128, 2);
    rel_kernel<<<rgrid, 256, REL_SMEM>>>(a_rel, m_rel, relp, num_center, num_src);

    scores_kernel<<<(num_edge + 7) / 8, 256>>>(idx, etype, num_edge);
    fused_agg_kernel<<<(num_center + 7) / 8, 256>>>(ptr, idx, etype, out, num_center);
}

// round 15
// speedup vs baseline: 1.0616x; 1.0616x over previous
#include <cuda_runtime.h>

#define HID 128
#define HEADS 4
#define DIM 32
#define NT 8
#define ETY 8

#define N_SRC_MAX 200000
#define N_CTR_MAX 100000
#define N_EDGE_MAX 800000
#define OSRC_LEN (N_SRC_MAX + 1024)
#define ODST_LEN (N_CTR_MAX + 1024)

typedef unsigned long long u64;

__device__ __forceinline__ u64 pk2(float x, float y) {
    u64 r; asm("mov.b64 %0,{%1,%2};" : "=l"(r) : "f"(x), "f"(y)); return r;
}
__device__ __forceinline__ void up2(float& x, float& y, u64 v) {
    asm("mov.b64 {%0,%1},%2;" : "=f"(x), "=f"(y) : "l"(v));
}
__device__ __forceinline__ u64 f2fma(u64 a, u64 b, u64 c) {
    u64 d; asm("fma.rn.f32x2 %0,%1,%2,%3;" : "=l"(d) : "l"(a), "l"(b), "l"(c)); return d;
}
__device__ __forceinline__ float tf32r(float x) {
    unsigned u; asm("cvt.rna.tf32.f32 %0, %1;" : "=r"(u) : "f"(x));
    return __uint_as_float(u);
}
__device__ __forceinline__ void mma_tf32(float* c, const unsigned* a, unsigned b0, unsigned b1) {
    asm("mma.sync.aligned.m16n8k8.row.col.f32.tf32.tf32.f32 "
        "{%0,%1,%2,%3}, {%4,%5,%6,%7}, {%8,%9}, {%0,%1,%2,%3};"
        : "+f"(c[0]), "+f"(c[1]), "+f"(c[2]), "+f"(c[3])
        : "r"(a[0]), "r"(a[1]), "r"(a[2]), "r"(a[3]), "r"(b0), "r"(b1));
}

// ---------------- scratch (device globals; no runtime allocation) ----------------
__device__ float g_k[(size_t)N_SRC_MAX * HID];
__device__ float g_v[(size_t)N_SRC_MAX * HID];
__device__ float g_q[(size_t)N_CTR_MAX * HID];
__device__ float g_qa[(size_t)N_CTR_MAX * ETY * HID];   // 410MB: (A[et] q[c]) * rp/sqrt(d)
__device__ float g_a[(size_t)N_EDGE_MAX * HEADS];       // edge scores
__device__ int   g_dstid[N_EDGE_MAX];
__device__ int   g_osrc[OSRC_LEN];
__device__ int   g_odst[ODST_LEN];
__device__ int   g_cnt[16];
__device__ int   g_pos[16];

// ---------------- prep (R12-exact) ----------------
__global__ void init_fill_kernel(const int* __restrict__ ptr, int C) {
    int i = blockIdx.x * blockDim.x + threadIdx.x;
    int stride = gridDim.x * blockDim.x;
    if (i < 16) { g_cnt[i] = 0; g_pos[i] = 0; }
    for (int j = i; j < OSRC_LEN; j += stride) g_osrc[j] = -1;
    for (int j = i; j < ODST_LEN; j += stride) g_odst[j] = -1;
    for (int c = i; c < C; c += stride) {
        int e0 = ptr[c], e1 = ptr[c + 1];
        for (int e = e0; e < e1; ++e) g_dstid[e] = c;
    }
}

__global__ void hist_kernel(const int* __restrict__ ntype, int num_src, int num_center) {
    __shared__ int sc[16];
    if (threadIdx.x < 16) sc[threadIdx.x] = 0;
    __syncthreads();
    int n = blockIdx.x * blockDim.x + threadIdx.x;
    if (n < num_src) {
        int t = ntype[n];
        atomicAdd(&sc[t], 1);
        if (n < num_center) atomicAdd(&sc[8 + t], 1);
    }
    __syncthreads();
    if (threadIdx.x < 16 && sc[threadIdx.x]) atomicAdd(&g_cnt[threadIdx.x], sc[threadIdx.x]);
}

__global__ void offsets_kernel() {
    if (threadIdx.x == 0 && blockIdx.x == 0) {
        int off = 0;
        for (int t = 0; t < 8; t++) { g_pos[t] = off; off += ((g_cnt[t] + 63) >> 6) << 6; }
        off = 0;
        for (int t = 0; t < 8; t++) { g_pos[8 + t] = off; off += ((g_cnt[8 + t] + 63) >> 6) << 6; }
    }
}

__global__ void scatter_kernel(const int* __restrict__ ntype, int num_src, int num_center) {
    __shared__ int sc[16];
    __shared__ int sb[16];
    if (threadIdx.x < 16) sc[threadIdx.x] = 0;
    __syncthreads();
    int n = blockIdx.x * blockDim.x + threadIdx.x;
    int t = 0, r1 = -1, r2 = -1;
    if (n < num_src) {
        t = ntype[n];
        r1 = atomicAdd(&sc[t], 1);
        if (n < num_center) r2 = atomicAdd(&sc[8 + t], 1);
    }
    __syncthreads();
    if (threadIdx.x < 16)
        sb[threadIdx.x] = sc[threadIdx.x] ? atomicAdd(&g_pos[threadIdx.x], sc[threadIdx.x]) : 0;
    __syncthreads();
    if (r1 >= 0) g_osrc[sb[t] + r1] = n;
    if (r2 >= 0) g_odst[sb[8 + t] + r2] = n;
}

// ---------------- typed node projection: tf32 tensor-core GEMM (R12-exact) ----------------
#define XS_STRIDE 132
#define WS_STRIDE 136
#define GEMM_SMEM ((64 * XS_STRIDE + 128 * WS_STRIDE) * 4)

__global__ void __launch_bounds__(256, 2) node_gemm_kernel(
    const float* __restrict__ x, const float* __restrict__ W8,
    const int* __restrict__ ntype, int which)
{
    extern __shared__ float sm[];
    float* xs = sm;
    float* ws = sm + 64 * XS_STRIDE;
    const int* order = (which == 2) ? g_odst : g_osrc;
    float* outp = (which == 0) ? g_k : (which == 1) ? g_v : g_q;

    const int base = blockIdx.x * 64;
    int n0 = order[base];
    if (n0 < 0) return;
    int t = ntype[n0];
    const int tid = threadIdx.x;

    const float4* Wg = (const float4*)(W8 + (size_t)t * 16384);
#pragma unroll
    for (int i = 0; i < 16; ++i) {
        int e4 = tid + i * 256;
        float4 w = Wg[e4];
        int k = e4 >> 5, n = (e4 & 31) << 2;
        float4 o = make_float4(tf32r(w.x), tf32r(w.y), tf32r(w.z), tf32r(w.w));
        *(float4*)(ws + k * WS_STRIDE + n) = o;
    }
    {
        int m = tid >> 2, q4 = tid & 3;
        int row = order[base + m];
#pragma unroll
        for (int it = 0; it < 8; ++it) {
            int k = q4 * 4 + it * 16;
            float4 xv = make_float4(0.f, 0.f, 0.f, 0.f);
            if (row >= 0) xv = *(const float4*)(x + (size_t)row * 128 + k);
            float4 o = make_float4(tf32r(xv.x), tf32r(xv.y), tf32r(xv.z), tf32r(xv.w));
            *(float4*)(xs + m * XS_STRIDE + k) = o;
        }
    }
    __syncthreads();

    const int lane = tid & 31, wid = tid >> 5;
    const int wm = (wid >> 2) * 32;
    const int wn = (wid & 3) * 32;
    const int g = lane >> 2, tig = lane & 3;

    float acc[2][4][4];
#pragma unroll
    for (int mt = 0; mt < 2; ++mt)
#pragma unroll
        for (int nt = 0; nt < 4; ++nt)
#pragma unroll
            for (int j = 0; j < 4; ++j) acc[mt][nt][j] = 0.f;

#pragma unroll 4
    for (int ks = 0; ks < 16; ++ks) {
        int kb = ks * 8;
        unsigned a[2][4];
#pragma unroll
        for (int mt = 0; mt < 2; ++mt) {
            const float* xr = xs + (wm + mt * 16 + g) * XS_STRIDE + kb;
            const float* xr8 = xr + 8 * XS_STRIDE;
            a[mt][0] = __float_as_uint(xr[tig]);
            a[mt][1] = __float_as_uint(xr8[tig]);
            a[mt][2] = __float_as_uint(xr[tig + 4]);
            a[mt][3] = __float_as_uint(xr8[tig + 4]);
        }
#pragma unroll
        for (int nt = 0; nt < 4; ++nt) {
            const float* wr = ws + (kb + tig) * WS_STRIDE + wn + nt * 8 + g;
            unsigned b0 = __float_as_uint(wr[0]);
            unsigned b1 = __float_as_uint(wr[4 * WS_STRIDE]);
            mma_tf32(acc[0][nt], a[0], b0, b1);
            mma_tf32(acc[1][nt], a[1], b0, b1);
        }
    }

#pragma unroll
    for (int mt = 0; mt < 2; ++mt) {
        int r0 = order[base + wm + mt * 16 + g];
        int r1 = order[base + wm + mt * 16 + g + 8];
#pragma unroll
        for (int nt = 0; nt < 4; ++nt) {
            int cn = wn + nt * 8 + 2 * tig;
            if (r0 >= 0) {
                float2 o = make_float2(acc[mt][nt][0], acc[mt][nt][1]);
                *(float2*)(outp + (size_t)r0 * 128 + cn) = o;
            }
            if (r1 >= 0) {
                float2 o = make_float2(acc[mt][nt][2], acc[mt][nt][3]);
                *(float2*)(outp + (size_t)r1 * 128 + cn) = o;
            }
        }
    }
}

// ---------------- relation transform (qa path, R12-exact) ----------------
#define QS_STRIDE 132
#define AS_STRIDE 36
#define REL_SMEM ((128 * QS_STRIDE + ETY * HEADS * DIM * AS_STRIDE) * 4)

__global__ void __launch_bounds__(256, 1) rel_kernel(
    const float* __restrict__ R, const float* __restrict__ relp,
    const float* __restrict__ src, float* __restrict__ dst, int N)
{
    extern __shared__ float sm[];
    float* qs = sm;
    float* as = sm + 128 * QS_STRIDE;
    const float inv = 0.17677669529663689f;
    const int tid = threadIdx.x;
    const int base = blockIdx.x * 128;

    for (int i = tid; i < ETY * HEADS * DIM * DIM; i += 256) {
        int et = i >> 12, h = (i >> 10) & 3, d = (i >> 5) & 31, f = i & 31;
        float sc = relp[h * ETY + et] * inv;
        as[((et * 4 + h) * 32 + f) * AS_STRIDE + d] = tf32r(R[i] * sc);
    }
    {
        int m = tid >> 1, half = tid & 1;
        int c = base + m;
#pragma unroll
        for (int j = 0; j < 16; ++j) {
            int k = half * 64 + j * 4;
            float4 v = make_float4(0.f, 0.f, 0.f, 0.f);
            if (c < N) v = *(const float4*)(src + (size_t)c * 128 + k);
            *(float4*)(qs + m * QS_STRIDE + k) =
                make_float4(tf32r(v.x), tf32r(v.y), tf32r(v.z), tf32r(v.w));
        }
    }
    __syncthreads();

    const int lane = tid & 31, et = tid >> 5;
    const int g = lane >> 2, tig = lane & 3;
#pragma unroll 1
    for (int h = 0; h < 4; ++h) {
        const float* ab = as + (size_t)(et * 4 + h) * 32 * AS_STRIDE;
#pragma unroll 1
        for (int mt = 0; mt < 8; ++mt) {
            float acc[4][4];
#pragma unroll
            for (int nt = 0; nt < 4; ++nt)
#pragma unroll
                for (int j = 0; j < 4; ++j) acc[nt][j] = 0.f;
#pragma unroll
            for (int ks = 0; ks < 4; ++ks) {
                int kb = h * 32 + ks * 8;
                const float* xr = qs + (mt * 16 + g) * QS_STRIDE + kb;
                unsigned a[4];
                a[0] = __float_as_uint(xr[tig]);
                a[1] = __float_as_uint(xr[8 * QS_STRIDE + tig]);
                a[2] = __float_as_uint(xr[tig + 4]);
                a[3] = __float_as_uint(xr[8 * QS_STRIDE + tig + 4]);
#pragma unroll
                for (int nt = 0; nt < 4; ++nt) {
                    const float* wr = ab + (ks * 8 + tig) * AS_STRIDE + nt * 8 + g;
                    mma_tf32(acc[nt], a, __float_as_uint(wr[0]),
                             __float_as_uint(wr[4 * AS_STRIDE]));
                }
            }
            int c0 = base + mt * 16 + g, c1 = c0 + 8;
#pragma unroll
            for (int nt = 0; nt < 4; ++nt) {
                int col = nt * 8 + 2 * tig;
                if (c0 < N)
                    *(float2*)(dst + (size_t)c0 * 1024 + et * 128 + h * 32 + col) =
                        make_float2(acc[nt][0], acc[nt][1]);
                if (c1 < N)
                    *(float2*)(dst + (size_t)c1 * 1024 + et * 128 + h * 32 + col) =
                        make_float2(acc[nt][2], acc[nt][3]);
            }
        }
    }
}

// ---------------- edge scores: warp per edge, fully coalesced gathers (R12-exact) ----------------
__global__ void __launch_bounds__(256) scores_kernel(
    const int* __restrict__ idx, const int* __restrict__ etype, int E)
{
    const unsigned FULL = 0xffffffffu;
    int w = (blockIdx.x * 256 + threadIdx.x) >> 5;
    if (w >= E) return;
    int lane = threadIdx.x & 31;
    int s = idx[w];
    int c = g_dstid[w];
    int et = etype[w];
    float4 kv = ((const float4*)(g_k + (size_t)s * HID))[lane];
    float4 qv = ((const float4*)(g_qa + ((size_t)c * 8 + et) * HID))[lane];
    u64 acc = f2fma(pk2(kv.x, kv.y), pk2(qv.x, qv.y), 0ull);
    acc = f2fma(pk2(kv.z, kv.w), pk2(qv.z, qv.w), acc);
    float lo, hi; up2(lo, hi, acc);
    float p = lo + hi;
    p += __shfl_xor_sync(FULL, p, 1);
    p += __shfl_xor_sync(FULL, p, 2);
    p += __shfl_xor_sync(FULL, p, 4);
    float val = __shfl_sync(FULL, p, (lane & 3) * 8);
    if (lane < 4) g_a[(size_t)w * 4 + lane] = val;
}

// ---------------- persistent fused agg: bucket accumulate + tensor-core M epilogue ----------------
// 148 blocks x 512 threads; M staged in smem ONCE per block; grid-stride over groups of 16 centers.
#define AGG_BLKC 16
#define S_STRIDE 1032
#define MS_STRIDE 36
#define AGG_SMEM ((AGG_BLKC * S_STRIDE + ETY * HEADS * DIM * MS_STRIDE) * 4)

__global__ void __launch_bounds__(512, 1) fused_agg_kernel(
    const int* __restrict__ ptr, const int* __restrict__ idx,
    const int* __restrict__ etype, const float* __restrict__ m_rel,
    float* __restrict__ out, int C)
{
    extern __shared__ float sm[];
    float* S = sm;                              // [16][1032]
    float* Msm = sm + AGG_BLKC * S_STRIDE;      // [(t*4+h)*32 + d][36] = M[t,h,d,f]

    const int tid = threadIdx.x;
    for (int i = tid; i < ETY * HEADS * DIM * DIM; i += 512) {
        int f = i & 31;
        int row = i >> 5;    // (t*4+h)*32 + d
        Msm[row * MS_STRIDE + f] = tf32r(m_rel[i]);
    }
    __syncthreads();

    const unsigned FULL = 0xffffffffu;
    const int lane = tid & 31;
    const int w = tid >> 5;            // warp = local center
    const int h = w & 3, nt = w >> 2;  // epilogue role
    const int g = lane >> 2, tig = lane & 3;
    const int ngroups = (C + AGG_BLKC - 1) / AGG_BLKC;

    for (int grp = blockIdx.x; grp < ngroups; grp += gridDim.x) {
        const int base = grp * AGG_BLKC;
        const int c = base + w;

        int e0 = 0, e1 = 0;
        if (c < C) { e0 = ptr[c]; e1 = ptr[c + 1]; }

        float sa[8][4];
#pragma unroll
        for (int t = 0; t < 8; ++t)
#pragma unroll
            for (int hh = 0; hh < 4; ++hh) sa[t][hh] = 0.f;

        if (e1 > e0) {
            int deg = e1 - e0;
            int h4 = lane & 3, el = lane >> 2;
            float mx = __int_as_float(0xff800000);
            for (int i = el; i < deg; i += 8) mx = fmaxf(mx, g_a[(size_t)(e0 + i) * 4 + h4]);
            mx = fmaxf(mx, __shfl_xor_sync(FULL, mx, 4));
            mx = fmaxf(mx, __shfl_xor_sync(FULL, mx, 8));
            mx = fmaxf(mx, __shfl_xor_sync(FULL, mx, 16));
            float den = 0.f;
            for (int i = el; i < deg; i += 8) den += __expf(g_a[(size_t)(e0 + i) * 4 + h4] - mx);
            den += __shfl_xor_sync(FULL, den, 4);
            den += __shfl_xor_sync(FULL, den, 8);
            den += __shfl_xor_sync(FULL, den, 16);
            float dinv = 1.f / den;
            float mxh[4], dih[4];
#pragma unroll
            for (int hh = 0; hh < 4; ++hh) {
                mxh[hh] = __shfl_sync(FULL, mx, hh);
                dih[hh] = __shfl_sync(FULL, dinv, hh);
            }

            for (int e = e0; e < e1; ++e) {
                int s = idx[e];
                int et = etype[e];
                float4 av = *(const float4*)(g_a + (size_t)e * 4);
                float al0 = __expf(av.x - mxh[0]) * dih[0];
                float al1 = __expf(av.y - mxh[1]) * dih[1];
                float al2 = __expf(av.z - mxh[2]) * dih[2];
                float al3 = __expf(av.w - mxh[3]) * dih[3];
                const float* vb = g_v + (size_t)s * HID;
                float v0 = vb[lane];
                float v1 = vb[32 + lane];
                float v2 = vb[64 + lane];
                float v3 = vb[96 + lane];
#define ACC_CASE(T) case T: \
                sa[T][0] = fmaf(al0, v0, sa[T][0]); \
                sa[T][1] = fmaf(al1, v1, sa[T][1]); \
                sa[T][2] = fmaf(al2, v2, sa[T][2]); \
                sa[T][3] = fmaf(al3, v3, sa[T][3]); break;
                switch (et) {
                    ACC_CASE(0) ACC_CASE(1) ACC_CASE(2) ACC_CASE(3)
                    ACC_CASE(4) ACC_CASE(5) ACC_CASE(6) ACC_CASE(7)
                }
#undef ACC_CASE
            }
        }

        // write bucket row to smem (tf32) — layout S[w][t*128 + h*32 + lane]
        float* Sr = S + w * S_STRIDE;
#pragma unroll
        for (int t = 0; t < 8; ++t)
#pragma unroll
            for (int hh = 0; hh < 4; ++hh)
                Sr[t * 128 + hh * 32 + lane] = tf32r(sa[t][hh]);

        __syncthreads();

        // tensor epilogue: warp w -> head h, n-tile nt (8 cols)
        float c4[4] = {0.f, 0.f, 0.f, 0.f};
#pragma unroll 1
        for (int t = 0; t < 8; ++t) {
            const int koff = t * 128 + h * 32;
            const float* Mb = Msm + (size_t)((t * 4 + h) * 32) * MS_STRIDE + nt * 8 + g;
#pragma unroll
            for (int ks = 0; ks < 4; ++ks) {
                int kb = ks * 8;
                unsigned a[4];
                a[0] = __float_as_uint(S[g * S_STRIDE + koff + kb + tig]);
                a[1] = __float_as_uint(S[(g + 8) * S_STRIDE + koff + kb + tig]);
                a[2] = __float_as_uint(S[g * S_STRIDE + koff + kb + tig + 4]);
                a[3] = __float_as_uint(S[(g + 8) * S_STRIDE + koff + kb + tig + 4]);
                unsigned b0 = __float_as_uint(Mb[(kb + tig) * MS_STRIDE]);
                unsigned b1 = __float_as_uint(Mb[(kb + tig + 4) * MS_STRIDE]);
                mma_tf32(c4, a, b0, b1);
            }
        }
        int c0 = base + g, c1 = base + g + 8;
        int col = h * 32 + nt * 8 + 2 * tig;
        if (c0 < C) *(float2*)(out + (size_t)c0 * 128 + col) = make_float2(c4[0], c4[1]);
        if (c1 < C) *(float2*)(out + (size_t)c1 * 128 + col) = make_float2(c4[2], c4[3]);

        __syncthreads();   // WAR: S reused next group
    }
}

// ---------------- host launcher ----------------
extern "C" void kernel_launch(void* const* d_in, const int* in_sizes, int n_in,
                              void* d_out, int out_size)
{
    (void)out_size;
    const float* x     = (const float*)d_in[0];
    const int*   ptr   = (const int*)d_in[1];
    const int*   idx   = (const int*)d_in[2];
    const int*   ntype = (const int*)d_in[3];
    const int*   etype = (const int*)d_in[4];
    int wb = n_in - 6;
    const float* k_lin = (const float*)d_in[wb + 0];
    const float* q_lin = (const float*)d_in[wb + 1];
    const float* v_lin = (const float*)d_in[wb + 2];
    const float* a_rel = (const float*)d_in[wb + 3];
    const float* m_rel = (const float*)d_in[wb + 4];
    const float* relp  = (const float*)d_in[wb + 5];

    int num_src    = in_sizes[3];
    int num_edge   = in_sizes[2];
    int num_center = in_sizes[1] - 1;
    float* out = (float*)d_out;

    cudaFuncSetAttribute(node_gemm_kernel, cudaFuncAttributeMaxDynamicSharedMemorySize, GEMM_SMEM);
    cudaFuncSetAttribute(rel_kernel,       cudaFuncAttributeMaxDynamicSharedMemorySize, REL_SMEM);
    cudaFuncSetAttribute(fused_agg_kernel, cudaFuncAttributeMaxDynamicSharedMemorySize, AGG_SMEM);

    float *pq, *pqa;
    cudaGetSymbolAddress((void**)&pq,  g_q);
    cudaGetSymbolAddress((void**)&pqa, g_qa);

    init_fill_kernel<<<600, 512>>>(ptr, num_center);
    hist_kernel<<<(num_src + 255) / 256, 256>>>(ntype, num_src, num_center);
    offsets_kernel<<<1, 32>>>();
    scatter_kernel<<<(num_src + 255) / 256, 256>>>(ntype, num_src, num_center);

    int tiles_src = (num_src + 63) / 64 + 8;
    int tiles_dst = (num_center + 63) / 64 + 8;
    node_gemm_kernel<<<tiles_src, 256, GEMM_SMEM>>>(x, k_lin, ntype, 0);
    node_gemm_kernel<<<tiles_src, 256, GEMM_SMEM>>>(x, v_lin, ntype, 1);
    node_gemm_kernel<<<tiles_dst, 256, GEMM_SMEM>>>(x, q_lin, ntype, 2);

    rel_kernel<<<(num_center + 127) / 128, 256, REL_SMEM>>>(a_rel, relp, pq, pqa, num_center);

    scores_kernel<<<(num_edge + 7) / 8, 256>>>(idx, etype, num_edge);
    fused_agg_kernel<<<148, 512, AGG_SMEM>>>(ptr, idx, etype, m_rel, out, num_center);
}

// round 16
// speedup vs baseline: 1.5202x; 1.4321x over previous
#include <cuda_runtime.h>

#define HID 128
#define HEADS 4
#define DIM 32
#define NT 8
#define ETY 8

#define N_SRC_MAX 200000
#define N_CTR_MAX 100000
#define N_EDGE_MAX 800000
#define OSRC_LEN (N_SRC_MAX + 1024)
#define ODST_LEN (N_CTR_MAX + 1024)

typedef unsigned long long u64;

__device__ __forceinline__ u64 pk2(float x, float y) {
    u64 r; asm("mov.b64 %0,{%1,%2};" : "=l"(r) : "f"(x), "f"(y)); return r;
}
__device__ __forceinline__ void up2(float& x, float& y, u64 v) {
    asm("mov.b64 {%0,%1},%2;" : "=f"(x), "=f"(y) : "l"(v));
}
__device__ __forceinline__ u64 f2fma(u64 a, u64 b, u64 c) {
    u64 d; asm("fma.rn.f32x2 %0,%1,%2,%3;" : "=l"(d) : "l"(a), "l"(b), "l"(c)); return d;
}
__device__ __forceinline__ float tf32r(float x) {
    unsigned u; asm("cvt.rna.tf32.f32 %0, %1;" : "=r"(u) : "f"(x));
    return __uint_as_float(u);
}
__device__ __forceinline__ void mma_tf32(float* c, const unsigned* a, unsigned b0, unsigned b1) {
    asm("mma.sync.aligned.m16n8k8.row.col.f32.tf32.tf32.f32 "
        "{%0,%1,%2,%3}, {%4,%5,%6,%7}, {%8,%9}, {%0,%1,%2,%3};"
        : "+f"(c[0]), "+f"(c[1]), "+f"(c[2]), "+f"(c[3])
        : "r"(a[0]), "r"(a[1]), "r"(a[2]), "r"(a[3]), "r"(b0), "r"(b1));
}

// ---------------- scratch (device globals; no runtime allocation) ----------------
__device__ float g_k[(size_t)N_SRC_MAX * HID];
__device__ float g_v[(size_t)N_SRC_MAX * HID];
__device__ float g_q[(size_t)N_CTR_MAX * HID];
__device__ float g_qa[(size_t)N_CTR_MAX * ETY * HID];   // 410MB: (A[et] q[c]) * rp/sqrt(d)
__device__ float g_vm[(size_t)N_SRC_MAX * ETY * HID];   // 820MB: v[s] @ M[et]
__device__ float g_a[(size_t)N_EDGE_MAX * HEADS];       // edge scores
__device__ int   g_dstid[N_EDGE_MAX];
__device__ int   g_osrc[OSRC_LEN];
__device__ int   g_odst[ODST_LEN];
__device__ int   g_cnt[16];
__device__ int   g_pos[16];

// ---------------- prep (R12-exact) ----------------
__global__ void init_fill_kernel(const int* __restrict__ ptr, int C) {
    int i = blockIdx.x * blockDim.x + threadIdx.x;
    int stride = gridDim.x * blockDim.x;
    if (i < 16) { g_cnt[i] = 0; g_pos[i] = 0; }
    for (int j = i; j < OSRC_LEN; j += stride) g_osrc[j] = -1;
    for (int j = i; j < ODST_LEN; j += stride) g_odst[j] = -1;
    for (int c = i; c < C; c += stride) {
        int e0 = ptr[c], e1 = ptr[c + 1];
        for (int e = e0; e < e1; ++e) g_dstid[e] = c;
    }
}

__global__ void hist_kernel(const int* __restrict__ ntype, int num_src, int num_center) {
    __shared__ int sc[16];
    if (threadIdx.x < 16) sc[threadIdx.x] = 0;
    __syncthreads();
    int n = blockIdx.x * blockDim.x + threadIdx.x;
    if (n < num_src) {
        int t = ntype[n];
        atomicAdd(&sc[t], 1);
        if (n < num_center) atomicAdd(&sc[8 + t], 1);
    }
    __syncthreads();
    if (threadIdx.x < 16 && sc[threadIdx.x]) atomicAdd(&g_cnt[threadIdx.x], sc[threadIdx.x]);
}

__global__ void offsets_kernel() {
    if (threadIdx.x == 0 && blockIdx.x == 0) {
        int off = 0;
        for (int t = 0; t < 8; t++) { g_pos[t] = off; off += ((g_cnt[t] + 63) >> 6) << 6; }
        off = 0;
        for (int t = 0; t < 8; t++) { g_pos[8 + t] = off; off += ((g_cnt[8 + t] + 63) >> 6) << 6; }
    }
}

__global__ void scatter_kernel(const int* __restrict__ ntype, int num_src, int num_center) {
    __shared__ int sc[16];
    __shared__ int sb[16];
    if (threadIdx.x < 16) sc[threadIdx.x] = 0;
    __syncthreads();
    int n = blockIdx.x * blockDim.x + threadIdx.x;
    int t = 0, r1 = -1, r2 = -1;
    if (n < num_src) {
        t = ntype[n];
        r1 = atomicAdd(&sc[t], 1);
        if (n < num_center) r2 = atomicAdd(&sc[8 + t], 1);
    }
    __syncthreads();
    if (threadIdx.x < 16)
        sb[threadIdx.x] = sc[threadIdx.x] ? atomicAdd(&g_pos[threadIdx.x], sc[threadIdx.x]) : 0;
    __syncthreads();
    if (r1 >= 0) g_osrc[sb[t] + r1] = n;
    if (r2 >= 0) g_odst[sb[8 + t] + r2] = n;
}

// ---------------- typed node projection: tf32 tensor-core GEMM (R12-exact) ----------------
#define XS_STRIDE 132
#define WS_STRIDE 136
#define GEMM_SMEM ((64 * XS_STRIDE + 128 * WS_STRIDE) * 4)

__global__ void __launch_bounds__(256, 2) node_gemm_kernel(
    const float* __restrict__ x, const float* __restrict__ W8,
    const int* __restrict__ ntype, int which)
{
    extern __shared__ float sm[];
    float* xs = sm;
    float* ws = sm + 64 * XS_STRIDE;
    const int* order = (which == 2) ? g_odst : g_osrc;
    float* outp = (which == 0) ? g_k : (which == 1) ? g_v : g_q;

    const int base = blockIdx.x * 64;
    int n0 = order[base];
    if (n0 < 0) return;
    int t = ntype[n0];
    const int tid = threadIdx.x;

    const float4* Wg = (const float4*)(W8 + (size_t)t * 16384);
#pragma unroll
    for (int i = 0; i < 16; ++i) {
        int e4 = tid + i * 256;
        float4 w = Wg[e4];
        int k = e4 >> 5, n = (e4 & 31) << 2;
        float4 o = make_float4(tf32r(w.x), tf32r(w.y), tf32r(w.z), tf32r(w.w));
        *(float4*)(ws + k * WS_STRIDE + n) = o;
    }
    {
        int m = tid >> 2, q4 = tid & 3;
        int row = order[base + m];
#pragma unroll
        for (int it = 0; it < 8; ++it) {
            int k = q4 * 4 + it * 16;
            float4 xv = make_float4(0.f, 0.f, 0.f, 0.f);
            if (row >= 0) xv = *(const float4*)(x + (size_t)row * 128 + k);
            float4 o = make_float4(tf32r(xv.x), tf32r(xv.y), tf32r(xv.z), tf32r(xv.w));
            *(float4*)(xs + m * XS_STRIDE + k) = o;
        }
    }
    __syncthreads();

    const int lane = tid & 31, wid = tid >> 5;
    const int wm = (wid >> 2) * 32;
    const int wn = (wid & 3) * 32;
    const int g = lane >> 2, tig = lane & 3;

    float acc[2][4][4];
#pragma unroll
    for (int mt = 0; mt < 2; ++mt)
#pragma unroll
        for (int nt = 0; nt < 4; ++nt)
#pragma unroll
            for (int j = 0; j < 4; ++j) acc[mt][nt][j] = 0.f;

#pragma unroll 4
    for (int ks = 0; ks < 16; ++ks) {
        int kb = ks * 8;
        unsigned a[2][4];
#pragma unroll
        for (int mt = 0; mt < 2; ++mt) {
            const float* xr = xs + (wm + mt * 16 + g) * XS_STRIDE + kb;
            const float* xr8 = xr + 8 * XS_STRIDE;
            a[mt][0] = __float_as_uint(xr[tig]);
            a[mt][1] = __float_as_uint(xr8[tig]);
            a[mt][2] = __float_as_uint(xr[tig + 4]);
            a[mt][3] = __float_as_uint(xr8[tig + 4]);
        }
#pragma unroll
        for (int nt = 0; nt < 4; ++nt) {
            const float* wr = ws + (kb + tig) * WS_STRIDE + wn + nt * 8 + g;
            unsigned b0 = __float_as_uint(wr[0]);
            unsigned b1 = __float_as_uint(wr[4 * WS_STRIDE]);
            mma_tf32(acc[0][nt], a[0], b0, b1);
            mma_tf32(acc[1][nt], a[1], b0, b1);
        }
    }

#pragma unroll
    for (int mt = 0; mt < 2; ++mt) {
        int r0 = order[base + wm + mt * 16 + g];
        int r1 = order[base + wm + mt * 16 + g + 8];
#pragma unroll
        for (int nt = 0; nt < 4; ++nt) {
            int cn = wn + nt * 8 + 2 * tig;
            if (r0 >= 0) {
                float2 o = make_float2(acc[mt][nt][0], acc[mt][nt][1]);
                *(float2*)(outp + (size_t)r0 * 128 + cn) = o;
            }
            if (r1 >= 0) {
                float2 o = make_float2(acc[mt][nt][2], acc[mt][nt][3]);
                *(float2*)(outp + (size_t)r1 * 128 + cn) = o;
            }
        }
    }
}

// ---------------- relation transform (merged qa/vm via grid.y, R12 math) ----------------
// y=0 (qa): dst[c,et,h,d] = sum_f A[et,h,d,f]*q[c,h,f] * rp[h,et]/sqrt(d)
// y=1 (vm): dst[s,et,h,f] = sum_d v[s,h,d]*M[et,h,d,f]
#define QS_STRIDE 132
#define AS_STRIDE 36
#define REL_SMEM ((128 * QS_STRIDE + ETY * HEADS * DIM * AS_STRIDE) * 4)

__global__ void __launch_bounds__(256, 1) rel_kernel(
    const float* __restrict__ a_rel, const float* __restrict__ m_rel,
    const float* __restrict__ relp, int num_center, int num_src)
{
    const int mode = blockIdx.y;                 // 0 = qa, 1 = vm
    const int N = mode ? num_src : num_center;
    const int base = blockIdx.x * 128;
    if (base >= N) return;

    extern __shared__ float sm[];
    float* qs = sm;
    float* as = sm + 128 * QS_STRIDE;
    const float inv = 0.17677669529663689f;
    const int tid = threadIdx.x;

    const float* R = mode ? m_rel : a_rel;
    const float* src = mode ? g_v : g_q;
    float* dst = mode ? g_vm : g_qa;

    for (int i = tid; i < ETY * HEADS * DIM * DIM; i += 256) {
        int et = i >> 12, h = (i >> 10) & 3, d = (i >> 5) & 31, f = i & 31;
        float sc = mode ? 1.0f : relp[h * ETY + et] * inv;
        int row = mode ? d : f;     // k-dimension
        int col = mode ? f : d;     // n-dimension
        as[((et * 4 + h) * 32 + row) * AS_STRIDE + col] = tf32r(R[i] * sc);
    }
    {
        int m = tid >> 1, half = tid & 1;
        int c = base + m;
#pragma unroll
        for (int j = 0; j < 16; ++j) {
            int k = half * 64 + j * 4;
            float4 v = make_float4(0.f, 0.f, 0.f, 0.f);
            if (c < N) v = *(const float4*)(src + (size_t)c * 128 + k);
            *(float4*)(qs + m * QS_STRIDE + k) =
                make_float4(tf32r(v.x), tf32r(v.y), tf32r(v.z), tf32r(v.w));
        }
    }
    __syncthreads();

    const int lane = tid & 31, et = tid >> 5;
    const int g = lane >> 2, tig = lane & 3;
#pragma unroll 1
    for (int h = 0; h < 4; ++h) {
        const float* ab = as + (size_t)(et * 4 + h) * 32 * AS_STRIDE;
#pragma unroll 1
        for (int mt = 0; mt < 8; ++mt) {
            float acc[4][4];
#pragma unroll
            for (int nt = 0; nt < 4; ++nt)
#pragma unroll
                for (int j = 0; j < 4; ++j) acc[nt][j] = 0.f;
#pragma unroll
            for (int ks = 0; ks < 4; ++ks) {
                int kb = h * 32 + ks * 8;
                const float* xr = qs + (mt * 16 + g) * QS_STRIDE + kb;
                unsigned a[4];
                a[0] = __float_as_uint(xr[tig]);
                a[1] = __float_as_uint(xr[8 * QS_STRIDE + tig]);
                a[2] = __float_as_uint(xr[tig + 4]);
                a[3] = __float_as_uint(xr[8 * QS_STRIDE + tig + 4]);
#pragma unroll
                for (int nt = 0; nt < 4; ++nt) {
                    const float* wr = ab + (ks * 8 + tig) * AS_STRIDE + nt * 8 + g;
                    mma_tf32(acc[nt], a, __float_as_uint(wr[0]),
                             __float_as_uint(wr[4 * AS_STRIDE]));
                }
            }
            int c0 = base + mt * 16 + g, c1 = c0 + 8;
#pragma unroll
            for (int nt = 0; nt < 4; ++nt) {
                int col = nt * 8 + 2 * tig;
                if (c0 < N)
                    *(float2*)(dst + (size_t)c0 * 1024 + et * 128 + h * 32 + col) =
                        make_float2(acc[nt][0], acc[nt][1]);
                if (c1 < N)
                    *(float2*)(dst + (size_t)c1 * 1024 + et * 128 + h * 32 + col) =
                        make_float2(acc[nt][2], acc[nt][3]);
            }
        }
    }
}

// ---------------- edge scores: warp per edge, fully coalesced gathers (R12-exact) ----------------
__global__ void __launch_bounds__(256) scores_kernel(
    const int* __restrict__ idx, const int* __restrict__ etype, int E)
{
    const unsigned FULL = 0xffffffffu;
    int w = (blockIdx.x * 256 + threadIdx.x) >> 5;
    if (w >= E) return;
    int lane = threadIdx.x & 31;
    int s = idx[w];
    int c = g_dstid[w];
    int et = etype[w];
    float4 kv = ((const float4*)(g_k + (size_t)s * HID))[lane];
    float4 qv = ((const float4*)(g_qa + ((size_t)c * 8 + et) * HID))[lane];
    u64 acc = f2fma(pk2(kv.x, kv.y), pk2(qv.x, qv.y), 0ull);
    acc = f2fma(pk2(kv.z, kv.w), pk2(qv.z, qv.w), acc);
    float lo, hi; up2(lo, hi, acc);
    float p = lo + hi;
    p += __shfl_xor_sync(FULL, p, 1);
    p += __shfl_xor_sync(FULL, p, 2);
    p += __shfl_xor_sync(FULL, p, 4);
    float val = __shfl_sync(FULL, p, (lane & 3) * 8);
    if (lane < 4) g_a[(size_t)w * 4 + lane] = val;
}

// ---------------- fused softmax + aggregation: warp per center, float4 vm gather ----------------
// Lane mapping in edge loop: head h = lane>>3, dims (lane&7)*4 .. +3. One LDG.128 per edge.
__global__ void __launch_bounds__(256) fused_agg_kernel(
    const int* __restrict__ ptr, const int* __restrict__ idx,
    const int* __restrict__ etype, float* __restrict__ out, int C)
{
    const unsigned FULL = 0xffffffffu;
    const int lane = threadIdx.x & 31;
    int c = (blockIdx.x * 256 + threadIdx.x) >> 5;
    if (c >= C) return;

    int e0 = ptr[c], e1 = ptr[c + 1];
    float4* ob4 = (float4*)(out + (size_t)c * HID);
    if (e1 <= e0) {
        ob4[lane] = make_float4(0.f, 0.f, 0.f, 0.f);
        return;
    }
    int deg = e1 - e0;

    // softmax stats (stat layout: h = lane&3, el = lane>>2; lane h<4 ends with head-h stats)
    int h4 = lane & 3, el = lane >> 2;
    float mx = __int_as_float(0xff800000);
    for (int i = el; i < deg; i += 8) mx = fmaxf(mx, g_a[(size_t)(e0 + i) * 4 + h4]);
    mx = fmaxf(mx, __shfl_xor_sync(FULL, mx, 4));
    mx = fmaxf(mx, __shfl_xor_sync(FULL, mx, 8));
    mx = fmaxf(mx, __shfl_xor_sync(FULL, mx, 16));
    float den = 0.f;
    for (int i = el; i < deg; i += 8) den += __expf(g_a[(size_t)(e0 + i) * 4 + h4] - mx);
    den += __shfl_xor_sync(FULL, den, 4);
    den += __shfl_xor_sync(FULL, den, 8);
    den += __shfl_xor_sync(FULL, den, 16);
    float dinv = 1.f / den;

    // this lane's head in the gather phase
    const int myh = lane >> 3;
    const float mh = __shfl_sync(FULL, mx, myh);
    const float dh = __shfl_sync(FULL, dinv, myh);

    u64 o01 = 0ull, o23 = 0ull;
    for (int e = e0; e < e1; ++e) {
        int s = idx[e];
        int et = etype[e];
        float av = g_a[(size_t)e * 4 + myh];              // 8-lane broadcast, 1 sector
        float al = __expf(av - mh) * dh;
        u64 al2 = pk2(al, al);
        float4 vv = ((const float4*)(g_vm + ((size_t)s * 8 + et) * HID))[lane];  // 1 LDG.128
        o01 = f2fma(al2, pk2(vv.x, vv.y), o01);
        o23 = f2fma(al2, pk2(vv.z, vv.w), o23);
    }
    float o0, o1, o2, o3;
    up2(o0, o1, o01);
    up2(o2, o3, o23);
    ob4[lane] = make_float4(o0, o1, o2, o3);
}

// ---------------- host launcher ----------------
extern "C" void kernel_launch(void* const* d_in, const int* in_sizes, int n_in,
                              void* d_out, int out_size)
{
    (void)out_size;
    const float* x     = (const float*)d_in[0];
    const int*   ptr   = (const int*)d_in[1];
    const int*   idx   = (const int*)d_in[2];
    const int*   ntype = (const int*)d_in[3];
    const int*   etype = (const int*)d_in[4];
    int wb = n_in - 6;
    const float* k_lin = (const float*)d_in[wb + 0];
    const float* q_lin = (const float*)d_in[wb + 1];
    const float* v_lin = (const float*)d_in[wb + 2];
    const float* a_rel = (const float*)d_in[wb + 3];
    const float* m_rel = (const float*)d_in[wb + 4];
    const float* relp  = (const float*)d_in[wb + 5];

    int num_src    = in_sizes[3];
    int num_edge   = in_sizes[2];
    int num_center = in_sizes[1] - 1;
    float* out = (float*)d_out;

    cudaFuncSetAttribute(node_gemm_kernel, cudaFuncAttributeMaxDynamicSharedMemorySize, GEMM_SMEM);
    cudaFuncSetAttribute(rel_kernel,       cudaFuncAttributeMaxDynamicSharedMemorySize, REL_SMEM);

    init_fill_kernel<<<600, 512>>>(ptr, num_center);
    hist_kernel<<<(num_src + 255) / 256, 256>>>(ntype, num_src, num_center);
    offsets_kernel<<<1, 32>>>();
    scatter_kernel<<<(num_src + 255) / 256, 256>>>(ntype, num_src, num_center);

    int tiles_src = (num_src + 63) / 64 + 8;
    int tiles_dst = (num_center + 63) / 64 + 8;
    node_gemm_kernel<<<tiles_src, 256, GEMM_SMEM>>>(x, k_lin, ntype, 0);
    node_gemm_kernel<<<tiles_src, 256, GEMM_SMEM>>>(x, v_lin, ntype, 1);
    node_gemm_kernel<<<tiles_dst, 256, GEMM_SMEM>>>(x, q_lin, ntype, 2);

    dim3 rgrid((num_src + 127) / 128, 2);
    rel_kernel<<<rgrid, 256, REL_SMEM>>>(a_rel, m_rel, relp, num_center, num_src);

    scores_kernel<<<(num_edge + 7) / 8, 256>>>(idx, etype, num_edge);
    fused_agg_kernel<<<(num_center + 7) / 8, 256>>>(ptr, idx, etype, out, num_center);
}

// round 17
// speedup vs baseline: 1.6917x; 1.1128x over previous
#include <cuda_runtime.h>
#include <cuda_fp16.h>

#define HID 128
#define HEADS 4
#define DIM 32
#define NT 8
#define ETY 8

#define N_SRC_MAX 200000
#define N_CTR_MAX 100000
#define N_EDGE_MAX 800000
#define OSRC_LEN (N_SRC_MAX + 1024)
#define ODST_LEN (N_CTR_MAX + 1024)

typedef unsigned long long u64;

__device__ __forceinline__ u64 pk2(float x, float y) {
    u64 r; asm("mov.b64 %0,{%1,%2};" : "=l"(r) : "f"(x), "f"(y)); return r;
}
__device__ __forceinline__ void up2(float& x, float& y, u64 v) {
    asm("mov.b64 {%0,%1},%2;" : "=f"(x), "=f"(y) : "l"(v));
}
__device__ __forceinline__ u64 f2fma(u64 a, u64 b, u64 c) {
    u64 d; asm("fma.rn.f32x2 %0,%1,%2,%3;" : "=l"(d) : "l"(a), "l"(b), "l"(c)); return d;
}
__device__ __forceinline__ float tf32r(float x) {
    unsigned u; asm("cvt.rna.tf32.f32 %0, %1;" : "=r"(u) : "f"(x));
    return __uint_as_float(u);
}
__device__ __forceinline__ void mma_tf32(float* c, const unsigned* a, unsigned b0, unsigned b1) {
    asm("mma.sync.aligned.m16n8k8.row.col.f32.tf32.tf32.f32 "
        "{%0,%1,%2,%3}, {%4,%5,%6,%7}, {%8,%9}, {%0,%1,%2,%3};"
        : "+f"(c[0]), "+f"(c[1]), "+f"(c[2]), "+f"(c[3])
        : "r"(a[0]), "r"(a[1]), "r"(a[2]), "r"(a[3]), "r"(b0), "r"(b1));
}

// ---------------- scratch (device globals; no runtime allocation) ----------------
__device__ float  g_k[(size_t)N_SRC_MAX * HID];
__device__ float  g_v[(size_t)N_SRC_MAX * HID];
__device__ float  g_q[(size_t)N_CTR_MAX * HID];
__device__ __half g_qa[(size_t)N_CTR_MAX * ETY * HID];  // 205MB fp16: (A[et] q[c]) * rp/sqrt(d)
__device__ __half g_vm[(size_t)N_SRC_MAX * ETY * HID];  // 410MB fp16: v[s] @ M[et]
__device__ float  g_a[(size_t)N_EDGE_MAX * HEADS];      // edge scores
__device__ int    g_dstid[N_EDGE_MAX];
__device__ int    g_osrc[OSRC_LEN];
__device__ int    g_odst[ODST_LEN];
__device__ int    g_cnt[16];
__device__ int    g_pos[16];

// ---------------- prep (R12-exact) ----------------
__global__ void init_fill_kernel(const int* __restrict__ ptr, int C) {
    int i = blockIdx.x * blockDim.x + threadIdx.x;
    int stride = gridDim.x * blockDim.x;
    if (i < 16) { g_cnt[i] = 0; g_pos[i] = 0; }
    for (int j = i; j < OSRC_LEN; j += stride) g_osrc[j] = -1;
    for (int j = i; j < ODST_LEN; j += stride) g_odst[j] = -1;
    for (int c = i; c < C; c += stride) {
        int e0 = ptr[c], e1 = ptr[c + 1];
        for (int e = e0; e < e1; ++e) g_dstid[e] = c;
    }
}

__global__ void hist_kernel(const int* __restrict__ ntype, int num_src, int num_center) {
    __shared__ int sc[16];
    if (threadIdx.x < 16) sc[threadIdx.x] = 0;
    __syncthreads();
    int n = blockIdx.x * blockDim.x + threadIdx.x;
    if (n < num_src) {
        int t = ntype[n];
        atomicAdd(&sc[t], 1);
        if (n < num_center) atomicAdd(&sc[8 + t], 1);
    }
    __syncthreads();
    if (threadIdx.x < 16 && sc[threadIdx.x]) atomicAdd(&g_cnt[threadIdx.x], sc[threadIdx.x]);
}

__global__ void offsets_kernel() {
    if (threadIdx.x == 0 && blockIdx.x == 0) {
        int off = 0;
        for (int t = 0; t < 8; t++) { g_pos[t] = off; off += ((g_cnt[t] + 63) >> 6) << 6; }
        off = 0;
        for (int t = 0; t < 8; t++) { g_pos[8 + t] = off; off += ((g_cnt[8 + t] + 63) >> 6) << 6; }
    }
}

__global__ void scatter_kernel(const int* __restrict__ ntype, int num_src, int num_center) {
    __shared__ int sc[16];
    __shared__ int sb[16];
    if (threadIdx.x < 16) sc[threadIdx.x] = 0;
    __syncthreads();
    int n = blockIdx.x * blockDim.x + threadIdx.x;
    int t = 0, r1 = -1, r2 = -1;
    if (n < num_src) {
        t = ntype[n];
        r1 = atomicAdd(&sc[t], 1);
        if (n < num_center) r2 = atomicAdd(&sc[8 + t], 1);
    }
    __syncthreads();
    if (threadIdx.x < 16)
        sb[threadIdx.x] = sc[threadIdx.x] ? atomicAdd(&g_pos[threadIdx.x], sc[threadIdx.x]) : 0;
    __syncthreads();
    if (r1 >= 0) g_osrc[sb[t] + r1] = n;
    if (r2 >= 0) g_odst[sb[8 + t] + r2] = n;
}

// ---------------- typed node projection: tf32 tensor-core GEMM (R12-exact) ----------------
#define XS_STRIDE 132
#define WS_STRIDE 136
#define GEMM_SMEM ((64 * XS_STRIDE + 128 * WS_STRIDE) * 4)

__global__ void __launch_bounds__(256, 2) node_gemm_kernel(
    const float* __restrict__ x, const float* __restrict__ W8,
    const int* __restrict__ ntype, int which)
{
    extern __shared__ float sm[];
    float* xs = sm;
    float* ws = sm + 64 * XS_STRIDE;
    const int* order = (which == 2) ? g_odst : g_osrc;
    float* outp = (which == 0) ? g_k : (which == 1) ? g_v : g_q;

    const int base = blockIdx.x * 64;
    int n0 = order[base];
    if (n0 < 0) return;
    int t = ntype[n0];
    const int tid = threadIdx.x;

    const float4* Wg = (const float4*)(W8 + (size_t)t * 16384);
#pragma unroll
    for (int i = 0; i < 16; ++i) {
        int e4 = tid + i * 256;
        float4 w = Wg[e4];
        int k = e4 >> 5, n = (e4 & 31) << 2;
        float4 o = make_float4(tf32r(w.x), tf32r(w.y), tf32r(w.z), tf32r(w.w));
        *(float4*)(ws + k * WS_STRIDE + n) = o;
    }
    {
        int m = tid >> 2, q4 = tid & 3;
        int row = order[base + m];
#pragma unroll
        for (int it = 0; it < 8; ++it) {
            int k = q4 * 4 + it * 16;
            float4 xv = make_float4(0.f, 0.f, 0.f, 0.f);
            if (row >= 0) xv = *(const float4*)(x + (size_t)row * 128 + k);
            float4 o = make_float4(tf32r(xv.x), tf32r(xv.y), tf32r(xv.z), tf32r(xv.w));
            *(float4*)(xs + m * XS_STRIDE + k) = o;
        }
    }
    __syncthreads();

    const int lane = tid & 31, wid = tid >> 5;
    const int wm = (wid >> 2) * 32;
    const int wn = (wid & 3) * 32;
    const int g = lane >> 2, tig = lane & 3;

    float acc[2][4][4];
#pragma unroll
    for (int mt = 0; mt < 2; ++mt)
#pragma unroll
        for (int nt = 0; nt < 4; ++nt)
#pragma unroll
            for (int j = 0; j < 4; ++j) acc[mt][nt][j] = 0.f;

#pragma unroll 4
    for (int ks = 0; ks < 16; ++ks) {
        int kb = ks * 8;
        unsigned a[2][4];
#pragma unroll
        for (int mt = 0; mt < 2; ++mt) {
            const float* xr = xs + (wm + mt * 16 + g) * XS_STRIDE + kb;
            const float* xr8 = xr + 8 * XS_STRIDE;
            a[mt][0] = __float_as_uint(xr[tig]);
            a[mt][1] = __float_as_uint(xr8[tig]);
            a[mt][2] = __float_as_uint(xr[tig + 4]);
            a[mt][3] = __float_as_uint(xr8[tig + 4]);
        }
#pragma unroll
        for (int nt = 0; nt < 4; ++nt) {
            const float* wr = ws + (kb + tig) * WS_STRIDE + wn + nt * 8 + g;
            unsigned b0 = __float_as_uint(wr[0]);
            unsigned b1 = __float_as_uint(wr[4 * WS_STRIDE]);
            mma_tf32(acc[0][nt], a[0], b0, b1);
            mma_tf32(acc[1][nt], a[1], b0, b1);
        }
    }

#pragma unroll
    for (int mt = 0; mt < 2; ++mt) {
        int r0 = order[base + wm + mt * 16 + g];
        int r1 = order[base + wm + mt * 16 + g + 8];
#pragma unroll
        for (int nt = 0; nt < 4; ++nt) {
            int cn = wn + nt * 8 + 2 * tig;
            if (r0 >= 0) {
                float2 o = make_float2(acc[mt][nt][0], acc[mt][nt][1]);
                *(float2*)(outp + (size_t)r0 * 128 + cn) = o;
            }
            if (r1 >= 0) {
                float2 o = make_float2(acc[mt][nt][2], acc[mt][nt][3]);
                *(float2*)(outp + (size_t)r1 * 128 + cn) = o;
            }
        }
    }
}

// ---------------- relation transform (merged qa/vm via grid.y), fp16 output ----------------
// y=0 (qa): dst[c,et,h,d] = sum_f A[et,h,d,f]*q[c,h,f] * rp[h,et]/sqrt(d)
// y=1 (vm): dst[s,et,h,f] = sum_d v[s,h,d]*M[et,h,d,f]
#define QS_STRIDE 132
#define AS_STRIDE 36
#define REL_SMEM ((128 * QS_STRIDE + ETY * HEADS * DIM * AS_STRIDE) * 4)

__global__ void __launch_bounds__(256, 1) rel_kernel(
    const float* __restrict__ a_rel, const float* __restrict__ m_rel,
    const float* __restrict__ relp, int num_center, int num_src)
{
    const int mode = blockIdx.y;                 // 0 = qa, 1 = vm
    const int N = mode ? num_src : num_center;
    const int base = blockIdx.x * 128;
    if (base >= N) return;

    extern __shared__ float sm[];
    float* qs = sm;
    float* as = sm + 128 * QS_STRIDE;
    const float inv = 0.17677669529663689f;
    const int tid = threadIdx.x;

    const float* R = mode ? m_rel : a_rel;
    const float* src = mode ? g_v : g_q;
    __half* dst = mode ? g_vm : g_qa;

    for (int i = tid; i < ETY * HEADS * DIM * DIM; i += 256) {
        int et = i >> 12, h = (i >> 10) & 3, d = (i >> 5) & 31, f = i & 31;
        float sc = mode ? 1.0f : relp[h * ETY + et] * inv;
        int row = mode ? d : f;     // k-dimension
        int col = mode ? f : d;     // n-dimension
        as[((et * 4 + h) * 32 + row) * AS_STRIDE + col] = tf32r(R[i] * sc);
    }
    {
        int m = tid >> 1, half = tid & 1;
        int c = base + m;
#pragma unroll
        for (int j = 0; j < 16; ++j) {
            int k = half * 64 + j * 4;
            float4 v = make_float4(0.f, 0.f, 0.f, 0.f);
            if (c < N) v = *(const float4*)(src + (size_t)c * 128 + k);
            *(float4*)(qs + m * QS_STRIDE + k) =
                make_float4(tf32r(v.x), tf32r(v.y), tf32r(v.z), tf32r(v.w));
        }
    }
    __syncthreads();

    const int lane = tid & 31, et = tid >> 5;
    const int g = lane >> 2, tig = lane & 3;
#pragma unroll 1
    for (int h = 0; h < 4; ++h) {
        const float* ab = as + (size_t)(et * 4 + h) * 32 * AS_STRIDE;
#pragma unroll 1
        for (int mt = 0; mt < 8; ++mt) {
            float acc[4][4];
#pragma unroll
            for (int nt = 0; nt < 4; ++nt)
#pragma unroll
                for (int j = 0; j < 4; ++j) acc[nt][j] = 0.f;
#pragma unroll
            for (int ks = 0; ks < 4; ++ks) {
                int kb = h * 32 + ks * 8;
                const float* xr = qs + (mt * 16 + g) * QS_STRIDE + kb;
                unsigned a[4];
                a[0] = __float_as_uint(xr[tig]);
                a[1] = __float_as_uint(xr[8 * QS_STRIDE + tig]);
                a[2] = __float_as_uint(xr[tig + 4]);
                a[3] = __float_as_uint(xr[8 * QS_STRIDE + tig + 4]);
#pragma unroll
                for (int nt = 0; nt < 4; ++nt) {
                    const float* wr = ab + (ks * 8 + tig) * AS_STRIDE + nt * 8 + g;
                    mma_tf32(acc[nt], a, __float_as_uint(wr[0]),
                             __float_as_uint(wr[4 * AS_STRIDE]));
                }
            }
            int c0 = base + mt * 16 + g, c1 = c0 + 8;
#pragma unroll
            for (int nt = 0; nt < 4; ++nt) {
                int col = nt * 8 + 2 * tig;
                if (c0 < N)
                    *(__half2*)(dst + (size_t)c0 * 1024 + et * 128 + h * 32 + col) =
                        __floats2half2_rn(acc[nt][0], acc[nt][1]);
                if (c1 < N)
                    *(__half2*)(dst + (size_t)c1 * 1024 + et * 128 + h * 32 + col) =
                        __floats2half2_rn(acc[nt][2], acc[nt][3]);
            }
        }
    }
}

// ---------------- edge scores: warp per edge, fp16 qa gather ----------------
__global__ void __launch_bounds__(256) scores_kernel(
    const int* __restrict__ idx, const int* __restrict__ etype, int E)
{
    const unsigned FULL = 0xffffffffu;
    int w = (blockIdx.x * 256 + threadIdx.x) >> 5;
    if (w >= E) return;
    int lane = threadIdx.x & 31;
    int s = idx[w];
    int c = g_dstid[w];
    int et = etype[w];
    float4 kv = ((const float4*)(g_k + (size_t)s * HID))[lane];
    uint2 qd = ((const uint2*)(g_qa + ((size_t)c * 8 + et) * HID))[lane];   // 4 halves
    float2 q01 = __half22float2(*(__half2*)&qd.x);
    float2 q23 = __half22float2(*(__half2*)&qd.y);
    u64 acc = f2fma(pk2(kv.x, kv.y), pk2(q01.x, q01.y), 0ull);
    acc = f2fma(pk2(kv.z, kv.w), pk2(q23.x, q23.y), acc);
    float lo, hi; up2(lo, hi, acc);
    float p = lo + hi;
    p += __shfl_xor_sync(FULL, p, 1);
    p += __shfl_xor_sync(FULL, p, 2);
    p += __shfl_xor_sync(FULL, p, 4);
    float val = __shfl_sync(FULL, p, (lane & 3) * 8);
    if (lane < 4) g_a[(size_t)w * 4 + lane] = val;
}

// ---------------- fused softmax + aggregation: warp per center, fp16 vm gather ----------------
__global__ void __launch_bounds__(256) fused_agg_kernel(
    const int* __restrict__ ptr, const int* __restrict__ idx,
    const int* __restrict__ etype, float* __restrict__ out, int C)
{
    const unsigned FULL = 0xffffffffu;
    const int lane = threadIdx.x & 31;
    int c = (blockIdx.x * 256 + threadIdx.x) >> 5;
    if (c >= C) return;

    int e0 = ptr[c], e1 = ptr[c + 1];
    float4* ob4 = (float4*)(out + (size_t)c * HID);
    if (e1 <= e0) {
        ob4[lane] = make_float4(0.f, 0.f, 0.f, 0.f);
        return;
    }
    int deg = e1 - e0;

    // softmax stats (stat layout: h = lane&3, el = lane>>2)
    int h4 = lane & 3, el = lane >> 2;
    float mx = __int_as_float(0xff800000);
    for (int i = el; i < deg; i += 8) mx = fmaxf(mx, g_a[(size_t)(e0 + i) * 4 + h4]);
    mx = fmaxf(mx, __shfl_xor_sync(FULL, mx, 4));
    mx = fmaxf(mx, __shfl_xor_sync(FULL, mx, 8));
    mx = fmaxf(mx, __shfl_xor_sync(FULL, mx, 16));
    float den = 0.f;
    for (int i = el; i < deg; i += 8) den += __expf(g_a[(size_t)(e0 + i) * 4 + h4] - mx);
    den += __shfl_xor_sync(FULL, den, 4);
    den += __shfl_xor_sync(FULL, den, 8);
    den += __shfl_xor_sync(FULL, den, 16);
    float dinv = 1.f / den;

    const int myh = lane >> 3;            // this lane's head in the gather phase
    const float mh = __shfl_sync(FULL, mx, myh);
    const float dh = __shfl_sync(FULL, dinv, myh);

    u64 o01 = 0ull, o23 = 0ull;
    for (int e = e0; e < e1; ++e) {
        int s = idx[e];
        int et = etype[e];
        float av = g_a[(size_t)e * 4 + myh];
        float al = __expf(av - mh) * dh;
        u64 al2 = pk2(al, al);
        uint2 vd = ((const uint2*)(g_vm + ((size_t)s * 8 + et) * HID))[lane];  // 4 halves, LDG.64
        float2 v01 = __half22float2(*(__half2*)&vd.x);
        float2 v23 = __half22float2(*(__half2*)&vd.y);
        o01 = f2fma(al2, pk2(v01.x, v01.y), o01);
        o23 = f2fma(al2, pk2(v23.x, v23.y), o23);
    }
    float o0, o1, o2, o3;
    up2(o0, o1, o01);
    up2(o2, o3, o23);
    ob4[lane] = make_float4(o0, o1, o2, o3);
}

// ---------------- host launcher ----------------
extern "C" void kernel_launch(void* const* d_in, const int* in_sizes, int n_in,
                              void* d_out, int out_size)
{
    (void)out_size;
    const float* x     = (const float*)d_in[0];
    const int*   ptr   = (const int*)d_in[1];
    const int*   idx   = (const int*)d_in[2];
    const int*   ntype = (const int*)d_in[3];
    const int*   etype = (const int*)d_in[4];
    int wb = n_in - 6;
    const float* k_lin = (const float*)d_in[wb + 0];
    const float* q_lin = (const float*)d_in[wb + 1];
    const float* v_lin = (const float*)d_in[wb + 2];
    const float* a_rel = (const float*)d_in[wb + 3];
    const float* m_rel = (const float*)d_in[wb + 4];
    const float* relp  = (const float*)d_in[wb + 5];

    int num_src    = in_sizes[3];
    int num_edge   = in_sizes[2];
    int num_center = in_sizes[1] - 1;
    float* out = (float*)d_out;

    cudaFuncSetAttribute(node_gemm_kernel, cudaFuncAttributeMaxDynamicSharedMemorySize, GEMM_SMEM);
    cudaFuncSetAttribute(rel_kernel,       cudaFuncAttributeMaxDynamicSharedMemorySize, REL_SMEM);

    init_fill_kernel<<<600, 512>>>(ptr, num_center);
    hist_kernel<<<(num_src + 255) / 256, 256>>>(ntype, num_src, num_center);
    offsets_kernel<<<1, 32>>>();
    scatter_kernel<<<(num_src + 255) / 256, 256>>>(ntype, num_src, num_center);

    int tiles_src = (num_src + 63) / 64 + 8;
    int tiles_dst = (num_center + 63) / 64 + 8;
    node_gemm_kernel<<<tiles_src, 256, GEMM_SMEM>>>(x, k_lin, ntype, 0);
    node_gemm_kernel<<<tiles_src, 256, GEMM_SMEM>>>(x, v_lin, ntype, 1);
    node_gemm_kernel<<<tiles_dst, 256, GEMM_SMEM>>>(x, q_lin, ntype, 2);

    dim3 rgrid((num_src + 127) / 128, 2);
    rel_kernel<<<rgrid, 256, REL_SMEM>>>(a_rel, m_rel, relp, num_center, num_src);

    scores_kernel<<<(num_edge + 7) / 8, 256>>>(idx, etype, num_edge);
    fused_agg_kernel<<<(num_center + 7) / 8, 256>>>(ptr, idx, etype, out, num_center);
}